// round 12
// baseline (speedup 1.0000x reference)
#include <cuda_runtime.h>
#include <cstdint>

#define BB 16
#define TT 512
#define DD 384
#define OUT_LEN 3584            // T * (MAX_DUR - 1)
#define ROW_BYTES (DD * 4)      // 1536
#define ROWS 16                 // output rows per block
#define BLOCKS_PER_B (OUT_LEN / ROWS)   // 224
#define NT 256
#define V4 (DD / 4)             // 96 float4 per row

// TMA-store gather at full occupancy: NT=256/ROWS=16 -> 8 CTA/SM (64 warps),
// scan amortized over 16 rows, LDG.128 -> STS -> single 24.5KB bulk store.
__global__ void __launch_bounds__(NT, 8)
lr_fused(const float* __restrict__ xs, const int* __restrict__ ds,
         const int* __restrict__ ilens, float* __restrict__ out) {
    __shared__ alignas(128) float4 buf[ROWS * V4];   // 24576 B
    __shared__ int csum[TT];
    __shared__ int wtot[8];
    __shared__ int srcs[ROWS];

    const int tid = threadIdx.x;
    const int lane = tid & 31;
    const int w = tid >> 5;               // 8 warps
    const int b = blockIdx.y;
    const int r0 = blockIdx.x * ROWS;

    // ---- masked duration load: 2 consecutive per thread ----
    const int ilen = __ldg(ilens + b);
    int2 dv = ((const int2*)(ds + b * TT))[tid];
    const int g0 = tid * 2;
    int d0 = (g0 + 0 < ilen) ? dv.x : 0;
    int d1 = (g0 + 1 < ilen) ? dv.y : 0;
    int p1 = d0 + d1;

    // ---- block inclusive scan -> csum ----
    int x = p1;
    #pragma unroll
    for (int off = 1; off < 32; off <<= 1) {
        int y = __shfl_up_sync(0xFFFFFFFFu, x, off);
        if (lane >= off) x += y;
    }
    if (lane == 31) wtot[w] = x;
    __syncthreads();
    int woff = 0;
    #pragma unroll
    for (int i = 0; i < 8; ++i) woff += (i < w) ? wtot[i] : 0;
    const int excl = woff + x - p1;
    csum[g0 + 0] = excl + d0;
    csum[g0 + 1] = excl + p1;
    __syncthreads();

    const int total = csum[TT - 1];
    const int p = min(max(total - r0, 0), ROWS);   // valid rows are a prefix

    // ---- searchsorted(csum, t, 'right'): 10 halvings for [0,512] ----
    if (tid < ROWS) {
        int s = -1;
        if (tid < p) {
            const int t = r0 + tid;
            int lo = 0, hi = TT;
            #pragma unroll
            for (int it = 0; it < 10; ++it) {
                int mid = (lo + hi) >> 1;
                if (csum[mid] <= t) lo = mid + 1; else hi = mid;
            }
            s = lo;
        }
        srcs[tid] = s;
    }
    __syncthreads();

    // ---- gather: 1536 float4 over 256 threads, 2 batches of 3 (regs<=32) ----
    const float4* __restrict__ xb = (const float4*)xs + (size_t)b * TT * V4;

    #pragma unroll
    for (int h = 0; h < 2; ++h) {
        float4 v[3];
        int fo[3];
        #pragma unroll
        for (int i = 0; i < 3; ++i) {
            const int f = tid + (h * 3 + i) * NT;
            const int rl = f / V4;                 // mul-shift (const div)
            const int c = f - rl * V4;
            const int s = srcs[rl];
            fo[i] = f;
            v[i] = make_float4(0.f, 0.f, 0.f, 0.f);
            if (s >= 0) v[i] = xb[s * V4 + c];     // coalesced LDG.128, dups hit L1
        }
        #pragma unroll
        for (int i = 0; i < 3; ++i)
            buf[fo[i]] = v[i];                     // STS.128 (smem port, not L1 STG)
    }
    __syncthreads();

    // ---- single TMA bulk store; release smem on read-drain ----
    if (tid == 0) {
        uint32_t buf_s = (uint32_t)__cvta_generic_to_shared(buf);
        asm volatile("fence.proxy.async.shared::cta;" ::: "memory");
        char* dst = (char*)(out + ((size_t)b * OUT_LEN + r0) * DD);
        asm volatile(
            "cp.async.bulk.global.shared::cta.bulk_group [%0], [%1], %2;"
            :: "l"(dst), "r"(buf_s), "r"((uint32_t)(ROWS * ROW_BYTES)) : "memory");
        asm volatile("cp.async.bulk.commit_group;" ::: "memory");
        asm volatile("cp.async.bulk.wait_group.read 0;" ::: "memory");
    }
}

extern "C" void kernel_launch(void* const* d_in, const int* in_sizes, int n_in,
                              void* d_out, int out_size) {
    const float* xs = (const float*)d_in[0];
    const int* ds = (const int*)d_in[1];
    const int* ilens = (const int*)d_in[2];
    float* out = (float*)d_out;

    dim3 grid(BLOCKS_PER_B, BB);    // (224, 16) = 3584 blocks
    lr_fused<<<grid, NT>>>(xs, ds, ilens, out);
}

// round 13
// speedup vs baseline: 1.0270x; 1.0270x over previous
#include <cuda_runtime.h>
#include <cstdint>

#define BB 16
#define TT 512
#define DD 384
#define OUT_LEN 3584            // T * (MAX_DUR - 1)
#define ROWS 16                 // output rows per block (2 per warp)
#define BLOCKS_PER_B (OUT_LEN / ROWS)   // 224
#define NT 256
#define V4 (DD / 4)             // 96 float4 per row

// Warp-per-row gather: minimal instruction overhead per byte.
// Per warp: 2 rows x (1 broadcast LDS + 3 LDG.128 + 3 STG.128), loads batched
// for MLP=6, warp-uniform pad predicate. Scan+search amortized over 16 rows.
__global__ void __launch_bounds__(NT, 8)
lr_fused(const float* __restrict__ xs, const int* __restrict__ ds,
         const int* __restrict__ ilens, float* __restrict__ out) {
    __shared__ int csum[TT];
    __shared__ int wtot[8];
    __shared__ int srcs[ROWS];

    const int tid = threadIdx.x;
    const int lane = tid & 31;
    const int w = tid >> 5;               // 8 warps
    const int b = blockIdx.y;
    const int r0 = blockIdx.x * ROWS;

    // ---- masked duration load: 2 consecutive per thread ----
    const int ilen = __ldg(ilens + b);
    int2 dv = ((const int2*)(ds + b * TT))[tid];
    const int g0 = tid * 2;
    int d0 = (g0 + 0 < ilen) ? dv.x : 0;
    int d1 = (g0 + 1 < ilen) ? dv.y : 0;
    int p1 = d0 + d1;

    // ---- block inclusive scan -> csum ----
    int x = p1;
    #pragma unroll
    for (int off = 1; off < 32; off <<= 1) {
        int y = __shfl_up_sync(0xFFFFFFFFu, x, off);
        if (lane >= off) x += y;
    }
    if (lane == 31) wtot[w] = x;
    __syncthreads();
    int woff = 0;
    #pragma unroll
    for (int i = 0; i < 8; ++i) woff += (i < w) ? wtot[i] : 0;
    const int excl = woff + x - p1;
    csum[g0 + 0] = excl + d0;
    csum[g0 + 1] = excl + p1;
    __syncthreads();

    const int total = csum[TT - 1];
    const int p = min(max(total - r0, 0), ROWS);   // valid rows are a prefix

    // ---- searchsorted(csum, t, 'right'): 10 halvings for [0,512] ----
    if (tid < ROWS) {
        int s = -1;
        if (tid < p) {
            const int t = r0 + tid;
            int lo = 0, hi = TT;
            #pragma unroll
            for (int it = 0; it < 10; ++it) {
                int mid = (lo + hi) >> 1;
                if (csum[mid] <= t) lo = mid + 1; else hi = mid;
            }
            s = lo;
        }
        srcs[tid] = s;
    }
    __syncthreads();

    // ---- warp-per-row gather: warp w handles rows 2w, 2w+1 ----
    const float4* __restrict__ xb = (const float4*)xs + (size_t)b * TT * V4;
    float4* __restrict__ ob = (float4*)out + ((size_t)b * OUT_LEN + r0) * V4;

    const int ra = 2 * w;
    const int rb = ra + 1;
    const int sa = srcs[ra];               // broadcast LDS (all lanes same addr)
    const int sb = srcs[rb];

    const float4 zero = make_float4(0.f, 0.f, 0.f, 0.f);
    float4 va0 = zero, va1 = zero, va2 = zero;
    float4 vb0 = zero, vb1 = zero, vb2 = zero;

    // Batch all 6 loads (warp-uniform predicates, MLP=6).
    if (sa >= 0) {
        const float4* sra = xb + sa * V4 + lane;
        va0 = sra[0]; va1 = sra[32]; va2 = sra[64];
    }
    if (sb >= 0) {
        const float4* srb = xb + sb * V4 + lane;
        vb0 = srb[0]; vb1 = srb[32]; vb2 = srb[64];
    }

    // 6 coalesced STG.128.
    float4* da = ob + ra * V4 + lane;
    float4* db = ob + rb * V4 + lane;
    da[0] = va0; da[32] = va1; da[64] = va2;
    db[0] = vb0; db[32] = vb1; db[64] = vb2;
}

extern "C" void kernel_launch(void* const* d_in, const int* in_sizes, int n_in,
                              void* d_out, int out_size) {
    const float* xs = (const float*)d_in[0];
    const int* ds = (const int*)d_in[1];
    const int* ilens = (const int*)d_in[2];
    float* out = (float*)d_out;

    dim3 grid(BLOCKS_PER_B, BB);    // (224, 16) = 3584 blocks
    lr_fused<<<grid, NT>>>(xs, ds, ilens, out);
}

// round 14
// speedup vs baseline: 1.1364x; 1.1065x over previous
#include <cuda_runtime.h>
#include <cstdint>

#define BB 16
#define TT 512
#define DD 384
#define OUT_LEN 3584            // T * (MAX_DUR - 1)
#define ROWS 16                 // output rows per block (2 per warp)
#define BLOCKS_PER_B (OUT_LEN / ROWS)   // 224
#define NT 256
#define V4 (DD / 4)             // 96 float4 per row

// R13 warp-per-row gather + scatter-based src resolution (no csum array, no
// binary search) + streaming stores.
__global__ void __launch_bounds__(NT, 8)
lr_fused(const float* __restrict__ xs, const int* __restrict__ ds,
         const int* __restrict__ ilens, float* __restrict__ out) {
    __shared__ int wtot[8];
    __shared__ int srcs[ROWS];

    const int tid = threadIdx.x;
    const int lane = tid & 31;
    const int w = tid >> 5;               // 8 warps
    const int b = blockIdx.y;
    const int r0 = blockIdx.x * ROWS;

    // ---- init srcs to pad ----
    if (tid < ROWS) srcs[tid] = -1;

    // ---- masked duration load: 2 consecutive per thread ----
    const int ilen = __ldg(ilens + b);
    int2 dv = ((const int2*)(ds + b * TT))[tid];
    const int g0 = tid * 2;
    int d0 = (g0 + 0 < ilen) ? dv.x : 0;
    int d1 = (g0 + 1 < ilen) ? dv.y : 0;
    int p1 = d0 + d1;

    // ---- block exclusive prefix via shfl scan ----
    int x = p1;
    #pragma unroll
    for (int off = 1; off < 32; off <<= 1) {
        int y = __shfl_up_sync(0xFFFFFFFFu, x, off);
        if (lane >= off) x += y;
    }
    if (lane == 31) wtot[w] = x;
    __syncthreads();                      // also orders srcs init
    int woff = 0;
    #pragma unroll
    for (int i = 0; i < 8; ++i) woff += (i < w) ? wtot[i] : 0;
    const int excl = woff + x - p1;       // rows before position g0

    // ---- scatter: position g0 covers [excl, excl+d0), g0+1 covers next ----
    {
        const int e0 = excl + d0;
        const int e1 = excl + p1;
        int j0 = max(excl, r0), j1 = min(e0, r0 + ROWS);
        #pragma unroll
        for (int k = 0; k < 7; ++k)       // d <= 7
            if (j0 + k < j1) srcs[j0 + k - r0] = g0;
        j0 = max(e0, r0); j1 = min(e1, r0 + ROWS);
        #pragma unroll
        for (int k = 0; k < 7; ++k)
            if (j0 + k < j1) srcs[j0 + k - r0] = g0 + 1;
    }
    __syncthreads();

    // ---- warp-per-row gather: warp w handles rows 2w, 2w+1 ----
    const float4* __restrict__ xb = (const float4*)xs + (size_t)b * TT * V4;
    float4* __restrict__ ob = (float4*)out + ((size_t)b * OUT_LEN + r0) * V4;

    const int ra = 2 * w;
    const int rb = ra + 1;
    const int sa = srcs[ra];              // broadcast LDS
    const int sb = srcs[rb];

    const float4 zero = make_float4(0.f, 0.f, 0.f, 0.f);
    float4 va0 = zero, va1 = zero, va2 = zero;
    float4 vb0 = zero, vb1 = zero, vb2 = zero;

    if (sa >= 0) {
        const float4* sra = xb + sa * V4 + lane;
        va0 = sra[0]; va1 = sra[32]; va2 = sra[64];
    }
    if (sb >= 0) {
        const float4* srb = xb + sb * V4 + lane;
        vb0 = srb[0]; vb1 = srb[32]; vb2 = srb[64];
    }

    // 6 coalesced streaming STG.128 (evict-first: write-once data).
    float4* da = ob + ra * V4 + lane;
    float4* db = ob + rb * V4 + lane;
    __stcs(da,      va0); __stcs(da + 32, va1); __stcs(da + 64, va2);
    __stcs(db,      vb0); __stcs(db + 32, vb1); __stcs(db + 64, vb2);
}

extern "C" void kernel_launch(void* const* d_in, const int* in_sizes, int n_in,
                              void* d_out, int out_size) {
    const float* xs = (const float*)d_in[0];
    const int* ds = (const int*)d_in[1];
    const int* ilens = (const int*)d_in[2];
    float* out = (float*)d_out;

    dim3 grid(BLOCKS_PER_B, BB);    // (224, 16) = 3584 blocks
    lr_fused<<<grid, NT>>>(xs, ds, ilens, out);
}

// round 15
// speedup vs baseline: 1.1559x; 1.0171x over previous
#include <cuda_runtime.h>
#include <cstdint>

#define BB 16
#define TT 512
#define DD 384
#define OUT_LEN 3584            // T * (MAX_DUR - 1)
#define ROWS 16                 // output rows per block (2 per warp)
#define BLOCKS_PER_B (OUT_LEN / ROWS)   // 224
#define NT 256
#define V4 (DD / 4)             // 96 float4 per row

// R13 kernel (scan + searchsorted + warp-per-row gather) with R14's
// evict-first streaming stores (__stcs): write-once output doesn't pollute L2.
__global__ void __launch_bounds__(NT, 8)
lr_fused(const float* __restrict__ xs, const int* __restrict__ ds,
         const int* __restrict__ ilens, float* __restrict__ out) {
    __shared__ int csum[TT];
    __shared__ int wtot[8];
    __shared__ int srcs[ROWS];

    const int tid = threadIdx.x;
    const int lane = tid & 31;
    const int w = tid >> 5;               // 8 warps
    const int b = blockIdx.y;
    const int r0 = blockIdx.x * ROWS;

    // ---- masked duration load: 2 consecutive per thread ----
    const int ilen = __ldg(ilens + b);
    int2 dv = ((const int2*)(ds + b * TT))[tid];
    const int g0 = tid * 2;
    int d0 = (g0 + 0 < ilen) ? dv.x : 0;
    int d1 = (g0 + 1 < ilen) ? dv.y : 0;
    int p1 = d0 + d1;

    // ---- block inclusive scan -> csum ----
    int x = p1;
    #pragma unroll
    for (int off = 1; off < 32; off <<= 1) {
        int y = __shfl_up_sync(0xFFFFFFFFu, x, off);
        if (lane >= off) x += y;
    }
    if (lane == 31) wtot[w] = x;
    __syncthreads();
    int woff = 0;
    #pragma unroll
    for (int i = 0; i < 8; ++i) woff += (i < w) ? wtot[i] : 0;
    const int excl = woff + x - p1;
    csum[g0 + 0] = excl + d0;
    csum[g0 + 1] = excl + p1;
    __syncthreads();

    const int total = csum[TT - 1];
    const int p = min(max(total - r0, 0), ROWS);   // valid rows are a prefix

    // ---- searchsorted(csum, t, 'right'): 10 halvings for [0,512] ----
    if (tid < ROWS) {
        int s = -1;
        if (tid < p) {
            const int t = r0 + tid;
            int lo = 0, hi = TT;
            #pragma unroll
            for (int it = 0; it < 10; ++it) {
                int mid = (lo + hi) >> 1;
                if (csum[mid] <= t) lo = mid + 1; else hi = mid;
            }
            s = lo;
        }
        srcs[tid] = s;
    }
    __syncthreads();

    // ---- warp-per-row gather: warp w handles rows 2w, 2w+1 ----
    const float4* __restrict__ xb = (const float4*)xs + (size_t)b * TT * V4;
    float4* __restrict__ ob = (float4*)out + ((size_t)b * OUT_LEN + r0) * V4;

    const int ra = 2 * w;
    const int rb = ra + 1;
    const int sa = srcs[ra];              // broadcast LDS
    const int sb = srcs[rb];

    const float4 zero = make_float4(0.f, 0.f, 0.f, 0.f);
    float4 va0 = zero, va1 = zero, va2 = zero;
    float4 vb0 = zero, vb1 = zero, vb2 = zero;

    // Batch all 6 loads (warp-uniform predicates, MLP=6).
    if (sa >= 0) {
        const float4* sra = xb + sa * V4 + lane;
        va0 = sra[0]; va1 = sra[32]; va2 = sra[64];
    }
    if (sb >= 0) {
        const float4* srb = xb + sb * V4 + lane;
        vb0 = srb[0]; vb1 = srb[32]; vb2 = srb[64];
    }

    // 6 coalesced evict-first STG.128.
    float4* da = ob + ra * V4 + lane;
    float4* db = ob + rb * V4 + lane;
    __stcs(da,      va0); __stcs(da + 32, va1); __stcs(da + 64, va2);
    __stcs(db,      vb0); __stcs(db + 32, vb1); __stcs(db + 64, vb2);
}

extern "C" void kernel_launch(void* const* d_in, const int* in_sizes, int n_in,
                              void* d_out, int out_size) {
    const float* xs = (const float*)d_in[0];
    const int* ds = (const int*)d_in[1];
    const int* ilens = (const int*)d_in[2];
    float* out = (float*)d_out;

    dim3 grid(BLOCKS_PER_B, BB);    // (224, 16) = 3584 blocks
    lr_fused<<<grid, NT>>>(xs, ds, ilens, out);
}